// round 5
// baseline (speedup 1.0000x reference)
#include <cuda_runtime.h>
#include <cuda_fp16.h>
#include <cstdint>

#define NN 8192
#define DD 128
#define K2C 20.6099286f       // 1/(0.07*ln2)
#define QSCALE 16.0f          // per-side fp8 scale
#define INV_QQ (1.0f / 256.0f)

// ---------------------------------------------------------------------------
__device__ uint32_t g_q[NN * 32];    // normalized feats, e4m3, [8192][128B] as u32
__device__ float    g_rowsum[NN];
__device__ float    g_pos[NN];

__device__ __forceinline__ uint32_t smem_u32(const void* p) {
    uint32_t a;
    asm("{ .reg .u64 t; cvta.to.shared.u64 t, %1; cvt.u32.u64 %0, t; }" : "=r"(a) : "l"(p));
    return a;
}
__device__ __forceinline__ float ex2f(float x) {
    float y; asm("ex2.approx.ftz.f32 %0, %1;" : "=f"(y) : "f"(x)); return y;
}
__device__ __forceinline__ void cp16(uint32_t dst, const void* src) {
    asm volatile("cp.async.cg.shared.global [%0], [%1], 16;" :: "r"(dst), "l"(src));
}
#define CP_COMMIT() asm volatile("cp.async.commit_group;" ::: "memory")
#define CP_WAIT(n)  asm volatile("cp.async.wait_group %0;" :: "n"(n) : "memory")

#define LDSM4(r0, r1, r2, r3, a) \
    asm volatile("ldmatrix.sync.aligned.m8n8.x4.shared.b16 {%0,%1,%2,%3}, [%4];" \
                 : "=r"(r0), "=r"(r1), "=r"(r2), "=r"(r3) : "r"(a))
// fp8 e4m3 MMA: m16n8k32, same reg counts as m16n8k16.f16, 2x MACs
#define MMAF8(d, a, b0v, b1v) \
    asm volatile("mma.sync.aligned.m16n8k32.row.col.f32.e4m3.e4m3.f32 " \
                 "{%0,%1,%2,%3},{%4,%5,%6,%7},{%8,%9},{%0,%1,%2,%3};" \
                 : "+f"((d)[0]), "+f"((d)[1]), "+f"((d)[2]), "+f"((d)[3]) \
                 : "r"((a)[0]), "r"((a)[1]), "r"((a)[2]), "r"((a)[3]), \
                   "r"(b0v), "r"(b1v))

// pack two floats -> e4m3x2 (b: low byte, a: high byte)
__device__ __forceinline__ uint32_t f2_e4m3(float hi, float lo) {
    uint32_t r;
    asm("{ .reg .b16 t; cvt.rn.satfinite.e4m3x2.f32 t, %1, %2; cvt.u32.u16 %0, t; }"
        : "=r"(r) : "f"(hi), "f"(lo));
    return r;
}

// ---------------------------------------------------------------------------
// Kernel 1: row L2-normalize -> e4m3 (scaled by QSCALE)
// ---------------------------------------------------------------------------
__global__ void norm_kernel(const float* __restrict__ feats) {
    int row  = blockIdx.x * 8 + (threadIdx.x >> 5);
    int lane = threadIdx.x & 31;
    float4 v = ((const float4*)(feats + (size_t)row * DD))[lane];
    float ss = v.x * v.x + v.y * v.y + v.z * v.z + v.w * v.w;
    #pragma unroll
    for (int o = 16; o; o >>= 1) ss += __shfl_xor_sync(0xffffffffu, ss, o);
    float inv = QSCALE / fmaxf(sqrtf(ss), 1e-8f);
    // bytes little-endian: x0,x1,x2,x3  (low pair first)
    uint32_t lo16 = f2_e4m3(v.y * inv, v.x * inv);
    uint32_t hi16 = f2_e4m3(v.w * inv, v.z * inv);
    g_q[(size_t)row * 32 + lane] = lo16 | (hi16 << 16);
    if (lane == 0) g_rowsum[row] = 0.0f;
}

// ---------------------------------------------------------------------------
// Kernel 2: persistent column sweep, fp8 MMA, cp.async double-buffered B
//   tiles: 128x128 e4m3 = 16KB each; smem A|B0|B1 = 48KB; 2 CTAs/SM
// ---------------------------------------------------------------------------
#define NT 4
#define SMEM_BYTES 49152

// async copy one 128x128 fp8 tile (16KB): 1024 16B chunks, 8 chunks/row
__device__ __forceinline__ void copy_tile_async(uint32_t smemBase,
                                                const uint4* __restrict__ src,
                                                int tid) {
    #pragma unroll
    for (int i = 0; i < 4; i++) {
        int idx = tid + i * 256;
        int r = idx >> 3, c = idx & 7;
        uint32_t dst = smemBase + (uint32_t)((r * 8 + (c ^ (r & 7))) << 4);
        cp16(dst, src + idx);
    }
}

__global__ void __launch_bounds__(256, 2) sim_kernel() {
    extern __shared__ uint4 sm4[];
    const int tid  = threadIdx.x;
    const int lane = tid & 31;
    const int wid  = tid >> 5;
    const int rowBase  = blockIdx.x * 128;
    const int colGroup = blockIdx.y * (NT * 128);
    const int warpM = wid & 1;
    const int warpN = wid >> 1;

    const uint32_t smA  = smem_u32(sm4);
    const uint32_t smB0 = smA + 16384;
    const uint32_t smB1 = smA + 32768;

    copy_tile_async(smA,  (const uint4*)g_q + (size_t)rowBase * 8, tid);
    copy_tile_async(smB0, (const uint4*)g_q + (size_t)colGroup * 8, tid);
    CP_COMMIT();
    copy_tile_async(smB1, (const uint4*)g_q + (size_t)(colGroup + 128) * 8, tid);
    CP_COMMIT();
    CP_WAIT(1);
    __syncthreads();

    // ldmatrix lane mapping (b16-equivalent view: row = 8 chunks of 16B)
    const int aRowL = warpM * 64 + (lane & 15);
    const int aCB   = lane >> 4;
    const int bRowL = warpN * 32 + ((lane & 7) | ((lane >> 1) & 8));
    const int bCB   = (lane >> 3) & 1;

    float racc[4][2];
    #pragma unroll
    for (int mi = 0; mi < 4; mi++) { racc[mi][0] = 0.0f; racc[mi][1] = 0.0f; }

    const int rBase0 = rowBase + warpM * 64 + (lane >> 2);
    const int cW     = warpN * 32 + (lane & 3) * 2;

    for (int t = 0; t < NT; t++) {
        const uint32_t smB = (t & 1) ? smB1 : smB0;
        const int colBase = colGroup + t * 128;

        float C[4][4][4];
        #pragma unroll
        for (int mi = 0; mi < 4; mi++)
            #pragma unroll
            for (int nj = 0; nj < 4; nj++)
                #pragma unroll
                for (int q = 0; q < 4; q++) C[mi][nj][q] = 0.0f;

        #pragma unroll
        for (int ks = 0; ks < 4; ks++) {            // 4 k-steps of 32 fp8
            uint32_t a[4][4], b[2][4];
            #pragma unroll
            for (int mi = 0; mi < 4; mi++) {
                int r = aRowL + mi * 16;
                int ch = 2 * ks + aCB;              // 16B chunk in 0..7
                LDSM4(a[mi][0], a[mi][1], a[mi][2], a[mi][3],
                      smA + r * 128 + ((ch ^ (r & 7)) << 4));
            }
            #pragma unroll
            for (int nh = 0; nh < 2; nh++) {
                int r = bRowL + nh * 16;
                int ch = 2 * ks + bCB;
                LDSM4(b[nh][0], b[nh][1], b[nh][2], b[nh][3],
                      smB + r * 128 + ((ch ^ (r & 7)) << 4));
            }
            #pragma unroll
            for (int mi = 0; mi < 4; mi++)
                #pragma unroll
                for (int nj = 0; nj < 4; nj++)
                    MMAF8(C[mi][nj], a[mi], b[nj >> 1][(nj & 1) * 2],
                          b[nj >> 1][(nj & 1) * 2 + 1]);
        }

        __syncthreads();
        if (t + 2 < NT) {
            copy_tile_async(smB, (const uint4*)g_q +
                            (size_t)(colGroup + (t + 2) * 128) * 8, tid);
            CP_COMMIT();
        }

        // epilogue: descale, shifted exp accumulate, capture positive
        #pragma unroll
        for (int mi = 0; mi < 4; mi++) {
            #pragma unroll
            for (int h = 0; h < 2; h++) {
                const int grow = rBase0 + mi * 16 + h * 8;
                const int pcol = grow ^ (NN / 2);
                float acc = 0.0f;
                #pragma unroll
                for (int nj = 0; nj < 4; nj++) {
                    #pragma unroll
                    for (int q = 0; q < 2; q++) {
                        const int gcol = colBase + cW + nj * 8 + q;
                        const float s = C[mi][nj][h * 2 + q] * INV_QQ;
                        if (gcol != grow) acc += ex2f((s - 1.0f) * K2C);
                        if (gcol == pcol) g_pos[grow] = s;
                    }
                }
                racc[mi][h] += acc;
            }
        }

        if (t + 1 < NT) {
            CP_WAIT(1);
            __syncthreads();
        }
    }

    #pragma unroll
    for (int mi = 0; mi < 4; mi++) {
        #pragma unroll
        for (int h = 0; h < 2; h++) {
            float v = racc[mi][h];
            v += __shfl_xor_sync(0xffffffffu, v, 1);
            v += __shfl_xor_sync(0xffffffffu, v, 2);
            if ((lane & 3) == 0)
                atomicAdd(&g_rowsum[rBase0 + mi * 16 + h * 8], v);
        }
    }
}

// ---------------------------------------------------------------------------
// Kernel 3: loss = mean( (1 - pos)/T + ln(rowsum) )
// ---------------------------------------------------------------------------
__global__ void finish_kernel(float* __restrict__ out) {
    __shared__ float red[1024];
    const int tid = threadIdx.x;
    float acc = 0.0f;
    for (int r = tid; r < NN; r += 1024)
        acc += (1.0f - g_pos[r]) * (1.0f / 0.07f) + logf(g_rowsum[r]);
    red[tid] = acc;
    __syncthreads();
    #pragma unroll
    for (int s = 512; s > 0; s >>= 1) {
        if (tid < s) red[tid] += red[tid + s];
        __syncthreads();
    }
    if (tid == 0) out[0] = red[0] / (float)NN;
}

// ---------------------------------------------------------------------------
extern "C" void kernel_launch(void* const* d_in, const int* in_sizes, int n_in,
                              void* d_out, int out_size) {
    const float* feats = (const float*)d_in[0];
    float* out = (float*)d_out;

    cudaFuncSetAttribute(sim_kernel, cudaFuncAttributeMaxDynamicSharedMemorySize,
                         SMEM_BYTES);

    norm_kernel<<<NN / 8, 256>>>(feats);
    dim3 grid(NN / 128, NN / (NT * 128));
    sim_kernel<<<grid, 256, SMEM_BYTES>>>();
    finish_kernel<<<1, 1024>>>(out);
}

// round 6
// speedup vs baseline: 1.5626x; 1.5626x over previous
#include <cuda_runtime.h>
#include <cuda_fp16.h>
#include <cstdint>

#define NN 8192
#define DD 128
#define K2C 20.6099286f    // 1/(0.07*ln2)

// ---------------------------------------------------------------------------
__device__ uint32_t g_h[NN * 64];    // normalized feats, fp16x2, [8192][64]
__device__ float    g_rowsum[NN];
__device__ float    g_pos[NN];

__device__ __forceinline__ uint32_t smem_u32(const void* p) {
    uint32_t a;
    asm("{ .reg .u64 t; cvta.to.shared.u64 t, %1; cvt.u32.u64 %0, t; }" : "=r"(a) : "l"(p));
    return a;
}
__device__ __forceinline__ float ex2f(float x) {
    float y; asm("ex2.approx.ftz.f32 %0, %1;" : "=f"(y) : "f"(x)); return y;
}
__device__ __forceinline__ float lg2f(float x) {
    float y; asm("lg2.approx.f32 %0, %1;" : "=f"(y) : "f"(x)); return y;
}
__device__ __forceinline__ void cp16(uint32_t dst, const void* src) {
    asm volatile("cp.async.cg.shared.global [%0], [%1], 16;" :: "r"(dst), "l"(src));
}
#define CP_COMMIT() asm volatile("cp.async.commit_group;" ::: "memory")
#define CP_WAIT0()  asm volatile("cp.async.wait_group 0;" ::: "memory")

#define LDSM4(r0, r1, r2, r3, a) \
    asm volatile("ldmatrix.sync.aligned.m8n8.x4.shared.b16 {%0,%1,%2,%3}, [%4];" \
                 : "=r"(r0), "=r"(r1), "=r"(r2), "=r"(r3) : "r"(a))
#define MMA16816(d, a, b0v, b1v) \
    asm volatile("mma.sync.aligned.m16n8k16.row.col.f32.f16.f16.f32 " \
                 "{%0,%1,%2,%3},{%4,%5,%6,%7},{%8,%9},{%0,%1,%2,%3};" \
                 : "+f"((d)[0]), "+f"((d)[1]), "+f"((d)[2]), "+f"((d)[3]) \
                 : "r"((a)[0]), "r"((a)[1]), "r"((a)[2]), "r"((a)[3]), \
                   "r"(b0v), "r"(b1v))

// ---------------------------------------------------------------------------
// Kernel 1: row L2-normalize -> fp16
// ---------------------------------------------------------------------------
__global__ void norm_kernel(const float* __restrict__ feats) {
    int row  = blockIdx.x * 8 + (threadIdx.x >> 5);
    int lane = threadIdx.x & 31;
    float4 v = ((const float4*)(feats + (size_t)row * DD))[lane];
    float ss = v.x * v.x + v.y * v.y + v.z * v.z + v.w * v.w;
    #pragma unroll
    for (int o = 16; o; o >>= 1) ss += __shfl_xor_sync(0xffffffffu, ss, o);
    float inv = 1.0f / fmaxf(sqrtf(ss), 1e-8f);
    __half2 p0 = __floats2half2_rn(v.x * inv, v.y * inv);
    __half2 p1 = __floats2half2_rn(v.z * inv, v.w * inv);
    uint2 pk;
    pk.x = *(uint32_t*)&p0;
    pk.y = *(uint32_t*)&p1;
    *(uint2*)(g_h + (size_t)row * 64 + lane * 2) = pk;
    if (lane == 0) g_rowsum[row] = 0.0f;
}

// ---------------------------------------------------------------------------
// Kernel 2: triangular tile sweep (rt <= ct), symmetric dual accumulation
//   2080 tiles of 128x128, fp16 mma, smem A|B = 64KB, 2 CTAs/SM
// ---------------------------------------------------------------------------
#define NTILE 64
#define NBLK  (NTILE * (NTILE + 1) / 2)      // 2080
#define SMEM_BYTES 65536

__device__ __forceinline__ void copy_tile_async(uint32_t smemBase,
                                                const uint4* __restrict__ src,
                                                int tid) {
    #pragma unroll
    for (int i = 0; i < 8; i++) {
        int idx = tid + i * 256;
        int r = idx >> 4, c = idx & 15;
        uint32_t dst = smemBase + (uint32_t)((r * 16 + (c ^ (r & 7))) << 4);
        cp16(dst, src + idx);
    }
}

__global__ void __launch_bounds__(256, 2) sim_kernel() {
    extern __shared__ uint4 sm4[];
    const int tid  = threadIdx.x;
    const int lane = tid & 31;
    const int wid  = tid >> 5;

    // ---- decode linear bid -> upper-triangle (rt, ct), rt <= ct ----
    int rt;
    {
        const int bid = blockIdx.x;
        float disc = (2.0f * NTILE + 1.0f) * (2.0f * NTILE + 1.0f) - 8.0f * (float)bid;
        rt = (int)((2.0f * NTILE + 1.0f - sqrtf(disc)) * 0.5f);
        if (rt > NTILE - 1) rt = NTILE - 1;
        while (rt * NTILE - rt * (rt - 1) / 2 > blockIdx.x) rt--;
        while ((rt + 1) * NTILE - (rt + 1) * rt / 2 <= (int)blockIdx.x) rt++;
    }
    const int ct = rt + ((int)blockIdx.x - (rt * NTILE - rt * (rt - 1) / 2));
    const int rowBase = rt * 128;
    const int colBase = ct * 128;
    const bool isDiag = (rt == ct);
    const bool hasPos = (ct == rt + 32);

    const uint32_t smA = smem_u32(sm4);
    const uint32_t smB = isDiag ? smA : (smA + 32768);

    copy_tile_async(smA, (const uint4*)g_h + (size_t)rowBase * 16, tid);
    if (!isDiag)
        copy_tile_async(smA + 32768, (const uint4*)g_h + (size_t)colBase * 16, tid);
    CP_COMMIT();
    CP_WAIT0();
    __syncthreads();

    const int warpM = wid & 1;
    const int warpN = wid >> 1;
    const int aRowL = warpM * 64 + (lane & 15);
    const int aCB   = lane >> 4;
    const int bRowL = warpN * 32 + ((lane & 7) | ((lane >> 1) & 8));
    const int bCB   = (lane >> 3) & 1;

    float C[4][4][4];
    #pragma unroll
    for (int mi = 0; mi < 4; mi++)
        #pragma unroll
        for (int nj = 0; nj < 4; nj++)
            #pragma unroll
            for (int q = 0; q < 4; q++) C[mi][nj][q] = 0.0f;

    #pragma unroll
    for (int ks = 0; ks < 8; ks++) {
        uint32_t a[4][4], b[2][4];
        #pragma unroll
        for (int mi = 0; mi < 4; mi++) {
            int r = aRowL + mi * 16;
            int ch = 2 * ks + aCB;
            LDSM4(a[mi][0], a[mi][1], a[mi][2], a[mi][3],
                  smA + r * 256 + ((ch ^ (r & 7)) << 4));
        }
        #pragma unroll
        for (int nh = 0; nh < 2; nh++) {
            int r = bRowL + nh * 16;
            int ch = 2 * ks + bCB;
            LDSM4(b[nh][0], b[nh][1], b[nh][2], b[nh][3],
                  smB + r * 256 + ((ch ^ (r & 7)) << 4));
        }
        #pragma unroll
        for (int mi = 0; mi < 4; mi++)
            #pragma unroll
            for (int nj = 0; nj < 4; nj++)
                MMA16816(C[mi][nj], a[mi], b[nj >> 1][(nj & 1) * 2],
                         b[nj >> 1][(nj & 1) * 2 + 1]);
    }

    // ---- epilogue: exp once, feed row acc (and col acc if off-diag) ----
    const int rBase0 = rowBase + warpM * 64 + (lane >> 2);
    const int cBase0 = colBase + warpN * 32 + (lane & 3) * 2;

    float racc[4][2];
    float cacc[4][2];
    #pragma unroll
    for (int u = 0; u < 4; u++) {
        racc[u][0] = racc[u][1] = 0.0f;
        cacc[u][0] = cacc[u][1] = 0.0f;
    }

    if (isDiag) {
        #pragma unroll
        for (int mi = 0; mi < 4; mi++)
            #pragma unroll
            for (int h = 0; h < 2; h++) {
                const int grow = rBase0 + mi * 16 + h * 8;
                float acc = 0.0f;
                #pragma unroll
                for (int nj = 0; nj < 4; nj++)
                    #pragma unroll
                    for (int q = 0; q < 2; q++) {
                        const int gcol = cBase0 + nj * 8 + q;
                        const float s = C[mi][nj][h * 2 + q];
                        if (gcol != grow) acc += ex2f((s - 1.0f) * K2C);
                    }
                racc[mi][h] += acc;
            }
    } else {
        #pragma unroll
        for (int mi = 0; mi < 4; mi++)
            #pragma unroll
            for (int h = 0; h < 2; h++) {
                const int grow = rBase0 + mi * 16 + h * 8;
                const int pcol = grow ^ (NN / 2);
                float acc = 0.0f;
                #pragma unroll
                for (int nj = 0; nj < 4; nj++)
                    #pragma unroll
                    for (int q = 0; q < 2; q++) {
                        const int gcol = cBase0 + nj * 8 + q;
                        const float s = C[mi][nj][h * 2 + q];
                        const float e = ex2f((s - 1.0f) * K2C);
                        acc += e;
                        cacc[nj][q] += e;
                        if (hasPos && gcol == pcol) {
                            g_pos[grow] = s;
                            g_pos[gcol] = s;
                        }
                    }
                racc[mi][h] += acc;
            }
    }

    // row reduction: lanes sharing a row (xor 1, 2), atomic from lane&3==0
    #pragma unroll
    for (int mi = 0; mi < 4; mi++)
        #pragma unroll
        for (int h = 0; h < 2; h++) {
            float v = racc[mi][h];
            v += __shfl_xor_sync(0xffffffffu, v, 1);
            v += __shfl_xor_sync(0xffffffffu, v, 2);
            if ((lane & 3) == 0)
                atomicAdd(&g_rowsum[rBase0 + mi * 16 + h * 8], v);
        }

    // column reduction (off-diag only): lanes sharing cols (xor 4, 8, 16)
    if (!isDiag) {
        #pragma unroll
        for (int nj = 0; nj < 4; nj++)
            #pragma unroll
            for (int q = 0; q < 2; q++) {
                float v = cacc[nj][q];
                v += __shfl_xor_sync(0xffffffffu, v, 4);
                v += __shfl_xor_sync(0xffffffffu, v, 8);
                v += __shfl_xor_sync(0xffffffffu, v, 16);
                if (lane < 4)
                    atomicAdd(&g_rowsum[cBase0 + nj * 8 + q], v);
            }
    }
}

// ---------------------------------------------------------------------------
// Kernel 3: loss = mean( (1 - pos)/T + ln(rowsum) )
// ---------------------------------------------------------------------------
__global__ void finish_kernel(float* __restrict__ out) {
    __shared__ float red[1024];
    const int tid = threadIdx.x;
    float acc = 0.0f;
    for (int r = tid; r < NN; r += 1024)
        acc += (1.0f - g_pos[r]) * (1.0f / 0.07f) + lg2f(g_rowsum[r]) * 0.69314718f;
    red[tid] = acc;
    __syncthreads();
    #pragma unroll
    for (int s = 512; s > 0; s >>= 1) {
        if (tid < s) red[tid] += red[tid + s];
        __syncthreads();
    }
    if (tid == 0) out[0] = red[0] / (float)NN;
}

// ---------------------------------------------------------------------------
extern "C" void kernel_launch(void* const* d_in, const int* in_sizes, int n_in,
                              void* d_out, int out_size) {
    const float* feats = (const float*)d_in[0];
    float* out = (float*)d_out;

    cudaFuncSetAttribute(sim_kernel, cudaFuncAttributeMaxDynamicSharedMemorySize,
                         SMEM_BYTES);

    norm_kernel<<<NN / 8, 256>>>(feats);
    sim_kernel<<<NBLK, 256, SMEM_BYTES>>>();
    finish_kernel<<<1, 1024>>>(out);
}